// round 13
// baseline (speedup 1.0000x reference)
#include <cuda_runtime.h>
#include <math_constants.h>

#define BB 64
#define CC 256
#define HWN 3136
#define NF4 784        // 3136 / 4
#define SS 64
#define KK 8
#define BC (BB*CC)

// scratch (device globals — no allocation allowed in kernel_launch)
__device__ float g_sum[BC];
__device__ float g_min[BC];
__device__ float g_max[BC];
__device__ float g_scale[BC];
__device__ float g_smin[BB];
__device__ float g_smax[BB];
__device__ float g_qs[BB];
__device__ float g_qz[BB];

// ---------------------------------------------------------------------------
// Pass 1: per-(b,c) sum / min / max over the 3136-element HW plane.
// One block per (b,c) row; float4 coalesced loads.
// ---------------------------------------------------------------------------
__global__ __launch_bounds__(256) void k_reduce(const float* __restrict__ x) {
    const int row = blockIdx.x;                       // b*C + c
    const float4* __restrict__ p =
        reinterpret_cast<const float4*>(x) + (size_t)row * NF4;

    float s  = 0.0f;
    float mn = CUDART_INF_F;
    float mx = -CUDART_INF_F;

    for (int i = threadIdx.x; i < NF4; i += 256) {
        float4 v = p[i];
        s  += (v.x + v.y) + (v.z + v.w);
        mn  = fminf(mn, fminf(fminf(v.x, v.y), fminf(v.z, v.w)));
        mx  = fmaxf(mx, fmaxf(fmaxf(v.x, v.y), fmaxf(v.z, v.w)));
    }
    // warp reduce
    #pragma unroll
    for (int o = 16; o; o >>= 1) {
        s  += __shfl_xor_sync(0xffffffffu, s, o);
        mn  = fminf(mn, __shfl_xor_sync(0xffffffffu, mn, o));
        mx  = fmaxf(mx, __shfl_xor_sync(0xffffffffu, mx, o));
    }
    __shared__ float ss[8], smn[8], smx[8];
    const int w = threadIdx.x >> 5, l = threadIdx.x & 31;
    if (l == 0) { ss[w] = s; smn[w] = mn; smx[w] = mx; }
    __syncthreads();
    if (threadIdx.x == 0) {
        float S = ss[0], MN = smn[0], MX = smx[0];
        #pragma unroll
        for (int i = 1; i < 8; i++) {
            S += ss[i]; MN = fminf(MN, smn[i]); MX = fmaxf(MX, smx[i]);
        }
        g_sum[row] = S;
        g_min[row] = MN;
        g_max[row] = MX;
    }
}

// ---------------------------------------------------------------------------
// Pass 2: one block per sample b.
//   pooled[c] = sum/HW ; h = relu(pooled @ w1^T + b1) ; scale = hsig(h @ w2^T + b2)
//   per-sample min/max of scale*x via scale*g_min / scale*g_max (scale >= 0).
// ---------------------------------------------------------------------------
__global__ __launch_bounds__(256) void k_se(const float* __restrict__ w1,
                                            const float* __restrict__ b1,
                                            const float* __restrict__ w2,
                                            const float* __restrict__ b2) {
    const int b = blockIdx.x;
    const int t = threadIdx.x;

    __shared__ float sp[CC];
    __shared__ float sh[SS];

    sp[t] = g_sum[b * CC + t] * (1.0f / (float)HWN);
    __syncthreads();

    if (t < SS) {
        float acc = b1[t];
        const float* __restrict__ wr = w1 + t * CC;
        #pragma unroll 8
        for (int c = 0; c < CC; c++) acc = fmaf(sp[c], wr[c], acc);
        sh[t] = fmaxf(acc, 0.0f);
    }
    __syncthreads();

    float acc = b2[t];
    const float* __restrict__ wr = w2 + t * SS;
    #pragma unroll 8
    for (int s = 0; s < SS; s++) acc = fmaf(sh[s], wr[s], acc);

    float sc = fminf(fmaxf(acc / 6.0f + 0.5f, 0.0f), 1.0f);   // hardsigmoid
    g_scale[b * CC + t] = sc;

    float vmn = sc * g_min[b * CC + t];   // scale >= 0 => min(scale*x) = scale*min(x)
    float vmx = sc * g_max[b * CC + t];

    #pragma unroll
    for (int o = 16; o; o >>= 1) {
        vmn = fminf(vmn, __shfl_xor_sync(0xffffffffu, vmn, o));
        vmx = fmaxf(vmx, __shfl_xor_sync(0xffffffffu, vmx, o));
    }
    __shared__ float rmn[8], rmx[8];
    const int w = t >> 5, l = t & 31;
    if (l == 0) { rmn[w] = vmn; rmx[w] = vmx; }
    __syncthreads();
    if (t == 0) {
        float MN = rmn[0], MX = rmx[0];
        #pragma unroll
        for (int i = 1; i < 8; i++) { MN = fminf(MN, rmn[i]); MX = fmaxf(MX, rmx[i]); }
        g_smin[b] = MN;
        g_smax[b] = MX;
    }
}

// ---------------------------------------------------------------------------
// Pass 3: cluster segment min/max, EMA, quant params -> per-sample s, z.
// Tiny: single thread.
// ---------------------------------------------------------------------------
__global__ void k_quantparams(const float* __restrict__ act_range,
                              const int* __restrict__ cinfo) {
    if (threadIdx.x != 0 || blockIdx.x != 0) return;

    int map[BB];
    int idx = 0;
    for (int k = 0; k < KK; k++) {
        int id  = cinfo[2 * k];
        int cnt = cinfo[2 * k + 1];
        for (int j = 0; j < cnt && idx < BB; j++) map[idx++] = id;
    }
    int last = (idx > 0) ? map[idx - 1] : 0;
    while (idx < BB) map[idx++] = last;

    float segmn[KK], segmx[KK];
    for (int k = 0; k < KK; k++) { segmn[k] = CUDART_INF_F; segmx[k] = -CUDART_INF_F; }
    for (int b = 0; b < BB; b++) {
        int k = map[b];
        segmn[k] = fminf(segmn[k], g_smin[b]);
        segmx[k] = fmaxf(segmx[k], g_smax[b]);
    }

    float qs[KK], qz[KK];
    for (int k = 0; k < KK; k++) {
        float nmn = act_range[2 * k]     * 0.995f + segmn[k] * 0.005f;
        float nmx = act_range[2 * k + 1] * 0.995f + segmx[k] * 0.005f;
        float s   = fmaxf((nmx - nmn) / 15.0f, 1e-8f);
        qs[k] = s;
        qz[k] = -rintf(nmn / s);
    }
    for (int b = 0; b < BB; b++) {
        g_qs[b] = qs[map[b]];
        g_qz[b] = qz[map[b]];
    }
}

// ---------------------------------------------------------------------------
// Pass 4: elementwise fake quantize: out = (clip(rint(sc*x/s + z),0,15)-z)*s
// One block per (b,c) row; float4 in/out.
// ---------------------------------------------------------------------------
__device__ __forceinline__ float fq(float v, float sc, float s, float z) {
    float o = v * sc;
    float q = rintf(o / s + z);
    q = fminf(fmaxf(q, 0.0f), 15.0f);
    return (q - z) * s;
}

__global__ __launch_bounds__(256) void k_quant(const float* __restrict__ x,
                                               float* __restrict__ out) {
    const int row = blockIdx.x;
    const int b   = row >> 8;                // / CC
    const float sc = g_scale[row];
    const float s  = g_qs[b];
    const float z  = g_qz[b];

    const float4* __restrict__ p = reinterpret_cast<const float4*>(x)   + (size_t)row * NF4;
    float4*       __restrict__ o = reinterpret_cast<float4*>(out)       + (size_t)row * NF4;

    for (int i = threadIdx.x; i < NF4; i += 256) {
        float4 v = p[i];
        float4 r;
        r.x = fq(v.x, sc, s, z);
        r.y = fq(v.y, sc, s, z);
        r.z = fq(v.z, sc, s, z);
        r.w = fq(v.w, sc, s, z);
        o[i] = r;
    }
}

// ---------------------------------------------------------------------------
extern "C" void kernel_launch(void* const* d_in, const int* in_sizes, int n_in,
                              void* d_out, int out_size) {
    const float* x   = (const float*)d_in[0];
    const float* w1  = (const float*)d_in[1];
    const float* b1  = (const float*)d_in[2];
    const float* w2  = (const float*)d_in[3];
    const float* b2  = (const float*)d_in[4];
    const float* ar  = (const float*)d_in[5];
    const int*   ci  = (const int*)d_in[6];
    float*       out = (float*)d_out;

    k_reduce<<<BC, 256>>>(x);
    k_se<<<BB, 256>>>(w1, b1, w2, b2);
    k_quantparams<<<1, 32>>>(ar, ci);
    k_quant<<<BC, 256>>>(x, out);
}

// round 14
// speedup vs baseline: 1.1126x; 1.1126x over previous
#include <cuda_runtime.h>
#include <math_constants.h>

#define BB 64
#define CC 256
#define HWN 3136
#define NF4 784        // 3136 / 4
#define SS 64
#define KK 8
#define BC (BB*CC)

// scratch (device globals — no allocation allowed in kernel_launch)
__device__ float g_sum[BC];
__device__ float g_min[BC];
__device__ float g_max[BC];
__device__ float g_scale[BC];
__device__ float g_smin[BB];
__device__ float g_smax[BB];
__device__ float g_qs[BB];
__device__ float g_qz[BB];
__device__ unsigned g_ticket;   // zero-initialized; reset by last block each call

// ---------------------------------------------------------------------------
// Pass 1: per-(b,c) sum / min / max over the 3136-element HW plane.
// One block per (b,c) row. Fully unrolled: 3 front-batched float4 loads per
// thread + predicated tail (784 = 3*256 + 16) for max MLP.
// ---------------------------------------------------------------------------
__global__ __launch_bounds__(256) void k_reduce(const float* __restrict__ x) {
    const int row = blockIdx.x;                       // b*C + c
    const int t   = threadIdx.x;
    const float4* __restrict__ p =
        reinterpret_cast<const float4*>(x) + (size_t)row * NF4;

    const bool tail = (t < 16);
    // front-batch all loads (MLP=4)
    float4 v0 = p[t];
    float4 v1 = p[t + 256];
    float4 v2 = p[t + 512];
    float4 v3 = p[tail ? (768 + t) : t];              // L1-hit dup for non-tail

    float s  = (v0.x + v0.y) + (v0.z + v0.w)
             + (v1.x + v1.y) + (v1.z + v1.w)
             + (v2.x + v2.y) + (v2.z + v2.w);
    float mn = fminf(fminf(fminf(v0.x, v0.y), fminf(v0.z, v0.w)),
               fminf(fminf(fminf(v1.x, v1.y), fminf(v1.z, v1.w)),
                     fminf(fminf(v2.x, v2.y), fminf(v2.z, v2.w))));
    float mx = fmaxf(fmaxf(fmaxf(v0.x, v0.y), fmaxf(v0.z, v0.w)),
               fmaxf(fmaxf(fmaxf(v1.x, v1.y), fmaxf(v1.z, v1.w)),
                     fmaxf(fmaxf(v2.x, v2.y), fmaxf(v2.z, v2.w))));
    if (tail) {
        s  += (v3.x + v3.y) + (v3.z + v3.w);
        mn  = fminf(mn, fminf(fminf(v3.x, v3.y), fminf(v3.z, v3.w)));
        mx  = fmaxf(mx, fmaxf(fmaxf(v3.x, v3.y), fmaxf(v3.z, v3.w)));
    }

    #pragma unroll
    for (int o = 16; o; o >>= 1) {
        s  += __shfl_xor_sync(0xffffffffu, s, o);
        mn  = fminf(mn, __shfl_xor_sync(0xffffffffu, mn, o));
        mx  = fmaxf(mx, __shfl_xor_sync(0xffffffffu, mx, o));
    }
    __shared__ float ss[8], smn[8], smx[8];
    const int w = t >> 5, l = t & 31;
    if (l == 0) { ss[w] = s; smn[w] = mn; smx[w] = mx; }
    __syncthreads();
    if (t == 0) {
        float S = ss[0], MN = smn[0], MX = smx[0];
        #pragma unroll
        for (int i = 1; i < 8; i++) {
            S += ss[i]; MN = fminf(MN, smn[i]); MX = fmaxf(MX, smx[i]);
        }
        g_sum[row] = S;
        g_min[row] = MN;
        g_max[row] = MX;
    }
}

// ---------------------------------------------------------------------------
// Pass 2 (fused): one block per sample b.
//   SE MLP -> hardsigmoid scale; per-sample min/max of scale*x
//   (scale >= 0 => min/max(scale*x) = scale*min/max(x)).
// Last-arriving block computes cluster EMA + quant params inline
// (threadfence-reduction pattern), removing a separate launch.
// ---------------------------------------------------------------------------
__global__ __launch_bounds__(256) void k_se(const float* __restrict__ w1,
                                            const float* __restrict__ b1,
                                            const float* __restrict__ w2,
                                            const float* __restrict__ b2,
                                            const float* __restrict__ act_range,
                                            const int* __restrict__ cinfo) {
    const int b = blockIdx.x;
    const int t = threadIdx.x;

    __shared__ float sp[CC];
    __shared__ float sh[SS];

    sp[t] = g_sum[b * CC + t] * (1.0f / (float)HWN);
    __syncthreads();

    if (t < SS) {
        float acc = b1[t];
        const float* __restrict__ wr = w1 + t * CC;
        #pragma unroll 8
        for (int c = 0; c < CC; c++) acc = fmaf(sp[c], wr[c], acc);
        sh[t] = fmaxf(acc, 0.0f);
    }
    __syncthreads();

    float acc = b2[t];
    const float* __restrict__ wr = w2 + t * SS;
    #pragma unroll 8
    for (int s = 0; s < SS; s++) acc = fmaf(sh[s], wr[s], acc);

    float sc = fminf(fmaxf(acc / 6.0f + 0.5f, 0.0f), 1.0f);   // hardsigmoid
    g_scale[b * CC + t] = sc;

    float vmn = sc * g_min[b * CC + t];
    float vmx = sc * g_max[b * CC + t];

    #pragma unroll
    for (int o = 16; o; o >>= 1) {
        vmn = fminf(vmn, __shfl_xor_sync(0xffffffffu, vmn, o));
        vmx = fmaxf(vmx, __shfl_xor_sync(0xffffffffu, vmx, o));
    }
    __shared__ float rmn[8], rmx[8];
    __shared__ bool  s_last;
    const int w = t >> 5, l = t & 31;
    if (l == 0) { rmn[w] = vmn; rmx[w] = vmx; }
    __syncthreads();

    if (t == 0) {
        float MN = rmn[0], MX = rmx[0];
        #pragma unroll
        for (int i = 1; i < 8; i++) { MN = fminf(MN, rmn[i]); MX = fmaxf(MX, rmx[i]); }
        g_smin[b] = MN;
        g_smax[b] = MX;
        __threadfence();                               // publish before ticket
        unsigned old = atomicAdd(&g_ticket, 1u);
        s_last = (old == (unsigned)(BB - 1));
    }
    __syncthreads();

    if (s_last && t == 0) {
        __threadfence();                               // acquire all g_smin/g_smax

        int map[BB];
        int idx = 0;
        for (int k = 0; k < KK; k++) {
            int id  = cinfo[2 * k];
            int cnt = cinfo[2 * k + 1];
            for (int j = 0; j < cnt && idx < BB; j++) map[idx++] = id;
        }
        int last = (idx > 0) ? map[idx - 1] : 0;
        while (idx < BB) map[idx++] = last;

        float segmn[KK], segmx[KK];
        #pragma unroll
        for (int k = 0; k < KK; k++) { segmn[k] = CUDART_INF_F; segmx[k] = -CUDART_INF_F; }
        for (int bb = 0; bb < BB; bb++) {
            int k = map[bb];
            segmn[k] = fminf(segmn[k], g_smin[bb]);
            segmx[k] = fmaxf(segmx[k], g_smax[bb]);
        }

        float qs[KK], qz[KK];
        #pragma unroll
        for (int k = 0; k < KK; k++) {
            float nmn = act_range[2 * k]     * 0.995f + segmn[k] * 0.005f;
            float nmx = act_range[2 * k + 1] * 0.995f + segmx[k] * 0.005f;
            float s   = fmaxf((nmx - nmn) / 15.0f, 1e-8f);
            qs[k] = s;
            qz[k] = -rintf(nmn / s);
        }
        for (int bb = 0; bb < BB; bb++) {
            g_qs[bb] = qs[map[bb]];
            g_qz[bb] = qz[map[bb]];
        }
        g_ticket = 0;                                  // reset for next replay
        __threadfence();
    }
}

// ---------------------------------------------------------------------------
// Pass 3: elementwise fake quantize: out = (clip(rint(sc*x/s + z),0,15)-z)*s
// Rows processed in REVERSE so the first-scheduled blocks read the tail of x
// still resident in L2 from k_reduce. Streaming loads/stores (evict-first)
// keep the output traffic from evicting that tail.
// ---------------------------------------------------------------------------
__device__ __forceinline__ float fq(float v, float sc, float s, float z) {
    float o = v * sc;
    float q = rintf(o / s + z);
    q = fminf(fmaxf(q, 0.0f), 15.0f);
    return (q - z) * s;
}

__global__ __launch_bounds__(256) void k_quant(const float* __restrict__ x,
                                               float* __restrict__ out) {
    const int row = (BC - 1) - blockIdx.x;            // reverse order for L2 reuse
    const int b   = row >> 8;                         // / CC
    const float sc = g_scale[row];
    const float s  = g_qs[b];
    const float z  = g_qz[b];

    const float4* __restrict__ p = reinterpret_cast<const float4*>(x)   + (size_t)row * NF4;
    float4*       __restrict__ o = reinterpret_cast<float4*>(out)       + (size_t)row * NF4;

    for (int i = threadIdx.x; i < NF4; i += 256) {
        float4 v = __ldcs(&p[i]);
        float4 r;
        r.x = fq(v.x, sc, s, z);
        r.y = fq(v.y, sc, s, z);
        r.z = fq(v.z, sc, s, z);
        r.w = fq(v.w, sc, s, z);
        __stcs(&o[i], r);
    }
}

// ---------------------------------------------------------------------------
extern "C" void kernel_launch(void* const* d_in, const int* in_sizes, int n_in,
                              void* d_out, int out_size) {
    const float* x   = (const float*)d_in[0];
    const float* w1  = (const float*)d_in[1];
    const float* b1  = (const float*)d_in[2];
    const float* w2  = (const float*)d_in[3];
    const float* b2  = (const float*)d_in[4];
    const float* ar  = (const float*)d_in[5];
    const int*   ci  = (const int*)d_in[6];
    float*       out = (float*)d_out;

    k_reduce<<<BC, 256>>>(x);
    k_se<<<BB, 256>>>(w1, b1, w2, b2, ar, ci);
    k_quant<<<BC, 256>>>(x, out);
}